// round 7
// baseline (speedup 1.0000x reference)
#include <cuda_runtime.h>
#include <math.h>
#include <stdint.h>

// Problem constants
#define SLEN   2048
#define DHEAD  64
#define NGROUP 32          // h*B = 8*4
#define MROWS  8192        // B*S
#define DMODEL 512
#define QK_SCALE 0.04419417382415922f   // 1/sqrt(512)

// Static scratch (interleaved tf32 hi/lo buffers, 2x element count)
__device__ float g_xhl[(size_t)2 * MROWS * DMODEL];
__device__ float g_yhl[(size_t)2 * MROWS * DMODEL];
__device__ float g_Qhl[(size_t)2 * MROWS * DMODEL];  // pre-scaled by QK_SCALE
__device__ float g_Khl[(size_t)2 * MROWS * DMODEL];
__device__ float g_Vhl[(size_t)2 * MROWS * DMODEL];
__device__ float g_Ohl[(size_t)2 * MROWS * DMODEL];
__device__ float g_Ksum[NGROUP * DHEAD];

// ---------------------------------------------------------------------------
// tf32 helpers
// ---------------------------------------------------------------------------
__device__ __forceinline__ uint32_t f32_to_tf32(float x) {
    uint32_t r;
    asm("cvt.rna.tf32.f32 %0, %1;" : "=r"(r) : "f"(x));
    return r;
}
__device__ __forceinline__ float tf32f(float x) {
    return __uint_as_float(f32_to_tf32(x));
}
__device__ __forceinline__ void mma_tf32(float (&c)[4],
    uint32_t a0, uint32_t a1, uint32_t a2, uint32_t a3,
    uint32_t b0, uint32_t b1)
{
    asm volatile(
        "mma.sync.aligned.m16n8k8.row.col.f32.tf32.tf32.f32 "
        "{%0,%1,%2,%3}, {%4,%5,%6,%7}, {%8,%9}, {%0,%1,%2,%3};\n"
        : "+f"(c[0]), "+f"(c[1]), "+f"(c[2]), "+f"(c[3])
        : "r"(a0), "r"(a1), "r"(a2), "r"(a3), "r"(b0), "r"(b1));
}

// ---------------------------------------------------------------------------
// Pre-split: fp32 -> interleaved {tf32 hi, tf32 lo}
// ---------------------------------------------------------------------------
__global__ __launch_bounds__(256) void split_hl(
    const float* __restrict__ in, float* __restrict__ out)
{
    size_t i = (size_t)blockIdx.x * 256 + threadIdx.x;  // float4 index
    float4 v = ((const float4*)in)[i];
    float h0 = tf32f(v.x), h1 = tf32f(v.y), h2 = tf32f(v.z), h3 = tf32f(v.w);
    ((float4*)out)[2 * i]     = make_float4(h0, tf32f(v.x - h0), h1, tf32f(v.y - h1));
    ((float4*)out)[2 * i + 1] = make_float4(h2, tf32f(v.z - h2), h3, tf32f(v.w - h3));
}

__global__ void zero_ksum(float* Ksum) {
    int i = blockIdx.x * 1024 + threadIdx.x;
    if (i < NGROUP * DHEAD) Ksum[i] = 0.f;
}

// ---------------------------------------------------------------------------
// 3xtf32 GEMM, A pre-split in gmem (interleaved hi/lo), W split in-kernel.
// C[8192,512] = A @ W + bias. 128x128 tile, BK=32, 256 thr, warps 2x4.
// MODE 0: fp32 out. MODE 1: scale by QK_SCALE, write interleaved hi/lo.
// MODE 2: write interleaved hi/lo. MODE 3: MODE 2 + fused column-sum->Ksum.
// Shared memory is DYNAMIC (72.2 KB > 48 KB static limit).
// ---------------------------------------------------------------------------
#define AS 133
#define BS 37
#define GEMM_SMEM_FLOATS (2 * 32 * AS + 2 * 128 * BS + 64)
#define GEMM_SMEM_BYTES  (GEMM_SMEM_FLOATS * 4)

template<int MODE>
__global__ __launch_bounds__(256, 2) void gemm3b(
    const float* __restrict__ Ahl, const float* __restrict__ W,
    const float* __restrict__ bias, float* __restrict__ C,
    float* __restrict__ Ksum)
{
    extern __shared__ float gsm[];
    float* AhiT = gsm;                       // [32][133]  ([k][row])
    float* AloT = AhiT + 32 * AS;            // [32][133]
    float* Bhi  = AloT + 32 * AS;            // [128][37]  ([n][k])
    float* Blo  = Bhi + 128 * BS;            // [128][37]
    float* s_cs = Blo + 128 * BS;            // [64]

    const int tid = threadIdx.x;
    const int bx = blockIdx.x, by = blockIdx.y;
    const int warp = tid >> 5, lane = tid & 31;
    const int wm = warp >> 2, wn = warp & 3;
    const int lg = lane >> 2, la = lane & 3;

    if (MODE == 3 && tid < 64) s_cs[tid] = 0.f;

    float acc[4][4][4] = {};

    for (int k0 = 0; k0 < DMODEL; k0 += 32) {
        // A tile: 128 rows x 32 k, hi/lo from gmem (pure copy)
        #pragma unroll
        for (int l = 0; l < 16; l++) {
            int idx = tid + l * 256;
            int r = idx >> 5, k = idx & 31;
            float2 v = *(const float2*)(Ahl +
                2 * ((size_t)(by * 128 + r) * DMODEL + k0 + k));
            AhiT[k * AS + r] = v.x;
            AloT[k * AS + r] = v.y;
        }
        // B tile: 32 k x 128 n, split in-kernel
        #pragma unroll
        for (int l = 0; l < 16; l++) {
            int idx = tid + l * 256;
            int k = idx >> 7, n = idx & 127;
            float b = W[(size_t)(k0 + k) * DMODEL + bx * 128 + n];
            float h = tf32f(b);
            Bhi[n * BS + k] = h;
            Blo[n * BS + k] = tf32f(b - h);
        }
        __syncthreads();

        #pragma unroll
        for (int kk = 0; kk < 4; kk++) {
            uint32_t ahi[4][4], alo[4][4];
            #pragma unroll
            for (int mf = 0; mf < 4; mf++) {
                int r0 = wm * 64 + mf * 16 + lg;
                int c0 = kk * 8 + la;
                ahi[mf][0] = __float_as_uint(AhiT[c0 * AS + r0]);
                ahi[mf][1] = __float_as_uint(AhiT[c0 * AS + r0 + 8]);
                ahi[mf][2] = __float_as_uint(AhiT[(c0 + 4) * AS + r0]);
                ahi[mf][3] = __float_as_uint(AhiT[(c0 + 4) * AS + r0 + 8]);
                alo[mf][0] = __float_as_uint(AloT[c0 * AS + r0]);
                alo[mf][1] = __float_as_uint(AloT[c0 * AS + r0 + 8]);
                alo[mf][2] = __float_as_uint(AloT[(c0 + 4) * AS + r0]);
                alo[mf][3] = __float_as_uint(AloT[(c0 + 4) * AS + r0 + 8]);
            }
            #pragma unroll
            for (int nf = 0; nf < 4; nf++) {
                int n = wn * 32 + nf * 8 + lg;
                int c0 = kk * 8 + la;
                uint32_t bhi0 = __float_as_uint(Bhi[n * BS + c0]);
                uint32_t bhi1 = __float_as_uint(Bhi[n * BS + c0 + 4]);
                uint32_t blo0 = __float_as_uint(Blo[n * BS + c0]);
                uint32_t blo1 = __float_as_uint(Blo[n * BS + c0 + 4]);
                #pragma unroll
                for (int mf = 0; mf < 4; mf++) {
                    mma_tf32(acc[mf][nf], ahi[mf][0], ahi[mf][1], ahi[mf][2], ahi[mf][3], bhi0, bhi1);
                    mma_tf32(acc[mf][nf], alo[mf][0], alo[mf][1], alo[mf][2], alo[mf][3], bhi0, bhi1);
                    mma_tf32(acc[mf][nf], ahi[mf][0], ahi[mf][1], ahi[mf][2], ahi[mf][3], blo0, blo1);
                }
            }
        }
        __syncthreads();
    }

    // epilogue
    float csum[4][2];
    if (MODE == 3)
        #pragma unroll
        for (int nf = 0; nf < 4; nf++) { csum[nf][0] = 0.f; csum[nf][1] = 0.f; }

    #pragma unroll
    for (int mf = 0; mf < 4; mf++) {
        int r0 = by * 128 + wm * 64 + mf * 16 + lg;
        #pragma unroll
        for (int nf = 0; nf < 4; nf++) {
            int c = bx * 128 + wn * 32 + nf * 8 + 2 * la;
            float b0 = bias[c], b1 = bias[c + 1];
            float t0 = acc[mf][nf][0] + b0;
            float t1 = acc[mf][nf][1] + b1;
            float t2 = acc[mf][nf][2] + b0;
            float t3 = acc[mf][nf][3] + b1;
            if (MODE == 3) { csum[nf][0] += t0 + t2; csum[nf][1] += t1 + t3; }
            if (MODE == 0) {
                *(float2*)(C + (size_t)r0 * DMODEL + c)       = make_float2(t0, t1);
                *(float2*)(C + (size_t)(r0 + 8) * DMODEL + c) = make_float2(t2, t3);
            } else {
                if (MODE == 1) { t0 *= QK_SCALE; t1 *= QK_SCALE; t2 *= QK_SCALE; t3 *= QK_SCALE; }
                float h0 = tf32f(t0), h1 = tf32f(t1), h2 = tf32f(t2), h3 = tf32f(t3);
                *(float4*)(C + 2 * ((size_t)r0 * DMODEL + c)) =
                    make_float4(h0, tf32f(t0 - h0), h1, tf32f(t1 - h1));
                *(float4*)(C + 2 * ((size_t)(r0 + 8) * DMODEL + c)) =
                    make_float4(h2, tf32f(t2 - h2), h3, tf32f(t3 - h3));
            }
        }
    }

    if (MODE == 3) {
        #pragma unroll
        for (int nf = 0; nf < 4; nf++) {
            atomicAdd(&s_cs[(wn * 32 + nf * 8 + 2 * la) & 63],     csum[nf][0]);
            atomicAdd(&s_cs[(wn * 32 + nf * 8 + 2 * la + 1) & 63], csum[nf][1]);
        }
        __syncthreads();
        if (tid < 64) atomicAdd(&Ksum[(by >> 1) * 64 + tid], s_cs[tid]);
    }
}

// ---------------------------------------------------------------------------
// Fused attention v2: block = (group g, 128-q tile); warp = 16 q-rows, full
// key range. Q frags in registers; K,V pre-split hi/lo in smem; P stays in
// registers (C-frag -> A-frag via shuffles); V 2x-split in P@V; no Z atomics.
// KVS MUST be a multiple of 4 (float4 smem stores) — 136 = mult of 8.
// ---------------------------------------------------------------------------
#define KVS 136
#define FUSED_SMEM ((2 * 128 * KVS + 64 + 128) * 4)

__global__ __launch_bounds__(256, 1) void fused_attn(
    const float* __restrict__ Qhl, const float* __restrict__ Khl,
    const float* __restrict__ Vhl, const float* __restrict__ Ksum,
    float* __restrict__ Ohl)
{
    extern __shared__ float sm[];
    float* Ks     = sm;                    // [128][136] interleaved hi/lo
    float* Vs     = Ks + 128 * KVS;        // [128][136] interleaved hi/lo
    float* s_ksum = Vs + 128 * KVS;        // 64
    float* s_mean = s_ksum + 64;           // 128

    const int tid = threadIdx.x;
    const int lane = tid & 31, w = tid >> 5;
    const int lg = lane >> 2, la = lane & 3;
    const int g = blockIdx.y, qt = blockIdx.x;

    const float* Qg = Qhl + 2 * ((size_t)(g * SLEN + qt * 128)) * DHEAD;
    const float* Kg = Khl + 2 * (size_t)g * SLEN * DHEAD;
    const float* Vg = Vhl + 2 * (size_t)g * SLEN * DHEAD;

    if (tid < 64) s_ksum[tid] = Ksum[g * 64 + tid];
    __syncthreads();
    if (tid < 128) {
        const float* qr = Qg + (size_t)tid * 128;
        float a = 0.f;
        #pragma unroll
        for (int d = 0; d < 64; d++) a += (qr[2 * d] + qr[2 * d + 1]) * s_ksum[d];
        s_mean[tid] = a * (1.0f / 2048.0f);
    }

    // Q fragments (constant over key tiles): rows w*16+lg, w*16+8+lg
    uint32_t qhi[8][4], qlo[8][4];
    {
        int r0 = w * 16 + lg;
        #pragma unroll
        for (int kk = 0; kk < 8; kk++) {
            int c0 = kk * 8 + la;
            float2 p;
            p = *(const float2*)(Qg + (size_t)r0 * 128 + 2 * c0);
            qhi[kk][0] = __float_as_uint(p.x); qlo[kk][0] = __float_as_uint(p.y);
            p = *(const float2*)(Qg + (size_t)(r0 + 8) * 128 + 2 * c0);
            qhi[kk][1] = __float_as_uint(p.x); qlo[kk][1] = __float_as_uint(p.y);
            p = *(const float2*)(Qg + (size_t)r0 * 128 + 2 * (c0 + 4));
            qhi[kk][2] = __float_as_uint(p.x); qlo[kk][2] = __float_as_uint(p.y);
            p = *(const float2*)(Qg + (size_t)(r0 + 8) * 128 + 2 * (c0 + 4));
            qhi[kk][3] = __float_as_uint(p.x); qlo[kk][3] = __float_as_uint(p.y);
        }
    }
    __syncthreads();
    const float m0 = s_mean[w * 16 + lg];
    const float m1 = s_mean[w * 16 + 8 + lg];

    float oacc[8][4] = {};
    float z0 = 0.f, z1 = 0.f;

    for (int kt = 0; kt < 16; kt++) {
        // load K,V interleaved tiles: 128 rows x 128 floats each
        #pragma unroll
        for (int l = 0; l < 16; l++) {
            int idx = tid + l * 256;
            int r = idx >> 5, c = (idx & 31) * 4;
            *(float4*)(Ks + r * KVS + c) =
                *(const float4*)(Kg + (size_t)(kt * 128 + r) * 128 + c);
            *(float4*)(Vs + r * KVS + c) =
                *(const float4*)(Vg + (size_t)(kt * 128 + r) * 128 + c);
        }
        __syncthreads();

        // === S = Q @ K^T (3xtf32), 16 independent n8 chunks ===
        float sc[16][4];
        #pragma unroll
        for (int nf = 0; nf < 16; nf++)
            #pragma unroll
            for (int j = 0; j < 4; j++) sc[nf][j] = 0.f;

        #pragma unroll
        for (int kk = 0; kk < 8; kk++) {
            int kc2 = 2 * (kk * 8 + la);
            #pragma unroll
            for (int nf = 0; nf < 16; nf++) {
                int kr = nf * 8 + lg;
                float2 b0 = *(const float2*)(Ks + kr * KVS + kc2);
                float2 b1 = *(const float2*)(Ks + kr * KVS + kc2 + 8);
                uint32_t bh0 = __float_as_uint(b0.x), bh1 = __float_as_uint(b1.x);
                uint32_t bl0 = __float_as_uint(b0.y), bl1 = __float_as_uint(b1.y);
                mma_tf32(sc[nf], qhi[kk][0], qhi[kk][1], qhi[kk][2], qhi[kk][3], bh0, bh1);
                mma_tf32(sc[nf], qlo[kk][0], qlo[kk][1], qlo[kk][2], qlo[kk][3], bh0, bh1);
                mma_tf32(sc[nf], qhi[kk][0], qhi[kk][1], qhi[kk][2], qhi[kk][3], bl0, bl1);
            }
        }

        // === mask + exp (tf32-rounded P kept in registers) ===
        #pragma unroll
        for (int nf = 0; nf < 16; nf++) {
            float s0 = sc[nf][0], s1 = sc[nf][1], s2 = sc[nf][2], s3 = sc[nf][3];
            float p0 = (s0 > m0) ? tf32f(__expf(s0)) : 0.f;
            float p1 = (s1 > m0) ? tf32f(__expf(s1)) : 0.f;
            float p2 = (s2 > m1) ? tf32f(__expf(s2)) : 0.f;
            float p3 = (s3 > m1) ? tf32f(__expf(s3)) : 0.f;
            z0 += p0 + p1; z1 += p2 + p3;
            sc[nf][0] = p0; sc[nf][1] = p1; sc[nf][2] = p2; sc[nf][3] = p3;
        }

        // === O += P @ V (V 2x-split), P repacked C-frag -> A-frag via shfl ===
        const int idx0 = lg * 4 + (la >> 1);
        const bool sel = (la & 1);
        #pragma unroll
        for (int t = 0; t < 16; t++) {
            float v00 = __shfl_sync(0xffffffffu, sc[t][0], idx0);
            float v01 = __shfl_sync(0xffffffffu, sc[t][1], idx0);
            float v10 = __shfl_sync(0xffffffffu, sc[t][2], idx0);
            float v11 = __shfl_sync(0xffffffffu, sc[t][3], idx0);
            float w00 = __shfl_sync(0xffffffffu, sc[t][0], idx0 + 2);
            float w01 = __shfl_sync(0xffffffffu, sc[t][1], idx0 + 2);
            float w10 = __shfl_sync(0xffffffffu, sc[t][2], idx0 + 2);
            float w11 = __shfl_sync(0xffffffffu, sc[t][3], idx0 + 2);
            uint32_t a0 = __float_as_uint(sel ? v01 : v00);
            uint32_t a1 = __float_as_uint(sel ? v11 : v10);
            uint32_t a2 = __float_as_uint(sel ? w01 : w00);
            uint32_t a3 = __float_as_uint(sel ? w11 : w10);
            int vr0 = (t * 8 + la) * KVS;
            int vr1 = (t * 8 + la + 4) * KVS;
            #pragma unroll
            for (int u = 0; u < 8; u++) {
                int vc2 = 2 * (u * 8 + lg);
                float2 bv0 = *(const float2*)(Vs + vr0 + vc2);
                float2 bv1 = *(const float2*)(Vs + vr1 + vc2);
                mma_tf32(oacc[u], a0, a1, a2, a3,
                         __float_as_uint(bv0.x), __float_as_uint(bv1.x));
                mma_tf32(oacc[u], a0, a1, a2, a3,
                         __float_as_uint(bv0.y), __float_as_uint(bv1.y));
            }
        }
        __syncthreads();
    }

    // Z reduce across the 4 la-lanes (rows are warp-exclusive)
    z0 += __shfl_xor_sync(0xffffffffu, z0, 1);
    z0 += __shfl_xor_sync(0xffffffffu, z0, 2);
    z1 += __shfl_xor_sync(0xffffffffu, z1, 1);
    z1 += __shfl_xor_sync(0xffffffffu, z1, 2);
    const float iz0 = 1.f / z0, iz1 = 1.f / z1;

    // normalize + split hi/lo + write interleaved O
    float* Og = Ohl + 2 * ((size_t)(g * SLEN + qt * 128)) * DHEAD;
    int r0 = w * 16 + lg;
    #pragma unroll
    for (int u = 0; u < 8; u++) {
        int c2 = 2 * (u * 8 + 2 * la);
        float t0 = oacc[u][0] * iz0, t1 = oacc[u][1] * iz0;
        float h0 = tf32f(t0), h1 = tf32f(t1);
        *(float4*)(Og + (size_t)r0 * 128 + c2) =
            make_float4(h0, tf32f(t0 - h0), h1, tf32f(t1 - h1));
        float t2 = oacc[u][2] * iz1, t3 = oacc[u][3] * iz1;
        float h2 = tf32f(t2), h3 = tf32f(t3);
        *(float4*)(Og + (size_t)(r0 + 8) * 128 + c2) =
            make_float4(h2, tf32f(t2 - h2), h3, tf32f(t3 - h3));
    }
}

// ---------------------------------------------------------------------------
// Launch. ncu profiles launch index 3 -> gemmQ this round.
// ---------------------------------------------------------------------------
extern "C" void kernel_launch(void* const* d_in, const int* in_sizes, int n_in,
                              void* d_out, int out_size)
{
    const float* x  = (const float*)d_in[0];
    const float* y  = (const float*)d_in[1];
    const float* Wq = (const float*)d_in[2];
    const float* bq = (const float*)d_in[3];
    const float* Wk = (const float*)d_in[4];
    const float* bk = (const float*)d_in[5];
    const float* Wv = (const float*)d_in[6];
    const float* bv = (const float*)d_in[7];
    const float* Wo = (const float*)d_in[8];
    const float* bo = (const float*)d_in[9];
    float* out = (float*)d_out;

    float *xhl, *yhl, *Qhl, *Khl, *Vhl, *Ohl, *KsumP;
    cudaGetSymbolAddress((void**)&xhl, g_xhl);
    cudaGetSymbolAddress((void**)&yhl, g_yhl);
    cudaGetSymbolAddress((void**)&Qhl, g_Qhl);
    cudaGetSymbolAddress((void**)&Khl, g_Khl);
    cudaGetSymbolAddress((void**)&Vhl, g_Vhl);
    cudaGetSymbolAddress((void**)&Ohl, g_Ohl);
    cudaGetSymbolAddress((void**)&KsumP, g_Ksum);

    cudaFuncSetAttribute(fused_attn,
                         cudaFuncAttributeMaxDynamicSharedMemorySize, FUSED_SMEM);
    cudaFuncSetAttribute(gemm3b<0>,
                         cudaFuncAttributeMaxDynamicSharedMemorySize, GEMM_SMEM_BYTES);
    cudaFuncSetAttribute(gemm3b<1>,
                         cudaFuncAttributeMaxDynamicSharedMemorySize, GEMM_SMEM_BYTES);
    cudaFuncSetAttribute(gemm3b<2>,
                         cudaFuncAttributeMaxDynamicSharedMemorySize, GEMM_SMEM_BYTES);
    cudaFuncSetAttribute(gemm3b<3>,
                         cudaFuncAttributeMaxDynamicSharedMemorySize, GEMM_SMEM_BYTES);

    dim3 gProj(DMODEL / 128, MROWS / 128);     // (4, 64)
    const int nsplit = MROWS * DMODEL / 4 / 256;  // 4096 blocks

    split_hl<<<nsplit, 256>>>(x, xhl);                                  // 0
    split_hl<<<nsplit, 256>>>(y, yhl);                                  // 1
    zero_ksum<<<2, 1024>>>(KsumP);                                      // 2
    gemm3b<1><<<gProj, 256, GEMM_SMEM_BYTES>>>(xhl, Wq, bq, Qhl, nullptr);   // 3  <- profiled
    gemm3b<3><<<gProj, 256, GEMM_SMEM_BYTES>>>(yhl, Wk, bk, Khl, KsumP);     // 4
    gemm3b<2><<<gProj, 256, GEMM_SMEM_BYTES>>>(yhl, Wv, bv, Vhl, nullptr);   // 5
    fused_attn<<<dim3(16, NGROUP), 256, FUSED_SMEM>>>(Qhl, Khl, Vhl, KsumP, Ohl); // 6
    gemm3b<0><<<gProj, 256, GEMM_SMEM_BYTES>>>(Ohl, Wo, bo, out, nullptr);   // 7
}

// round 8
// speedup vs baseline: 1.0448x; 1.0448x over previous
#include <cuda_runtime.h>
#include <math.h>
#include <stdint.h>

// Problem constants
#define SLEN   2048
#define DHEAD  64
#define NGROUP 32          // h*B = 8*4
#define MROWS  8192        // B*S
#define DMODEL 512
#define QK_SCALE 0.04419417382415922f   // 1/sqrt(512)

// Static scratch: interleaved {tf32 hi, tf32 lo} buffers (2x element count)
__device__ float g_Qhl[(size_t)2 * MROWS * DMODEL];  // pre-scaled by QK_SCALE
__device__ float g_Khl[(size_t)2 * MROWS * DMODEL];
__device__ float g_Vhl[(size_t)2 * MROWS * DMODEL];
__device__ float g_Ohl[(size_t)2 * MROWS * DMODEL];
__device__ float g_Ksum[NGROUP * DHEAD];

// ---------------------------------------------------------------------------
// tf32 helpers
// ---------------------------------------------------------------------------
__device__ __forceinline__ uint32_t f32_to_tf32(float x) {
    uint32_t r;
    asm("cvt.rna.tf32.f32 %0, %1;" : "=r"(r) : "f"(x));
    return r;
}
__device__ __forceinline__ float tf32f(float x) {
    return __uint_as_float(f32_to_tf32(x));
}
__device__ __forceinline__ void mma_tf32(float (&c)[4],
    uint32_t a0, uint32_t a1, uint32_t a2, uint32_t a3,
    uint32_t b0, uint32_t b1)
{
    asm volatile(
        "mma.sync.aligned.m16n8k8.row.col.f32.tf32.tf32.f32 "
        "{%0,%1,%2,%3}, {%4,%5,%6,%7}, {%8,%9}, {%0,%1,%2,%3};\n"
        : "+f"(c[0]), "+f"(c[1]), "+f"(c[2]), "+f"(c[3])
        : "r"(a0), "r"(a1), "r"(a2), "r"(a3), "r"(b0), "r"(b1));
}

// ---------------------------------------------------------------------------
// 4xtf32 GEMM (~fp32-exact): C = A[8192,512] @ W[512,512] + bias.
// AHL=0: A is fp32, split during tile load. AHL=1: A pre-split interleaved.
// MODE 0: fp32 out.  MODE 1: scale by QK_SCALE, interleaved hi/lo out,
//         block (0,0) zeroes Ksum first.  MODE 2: interleaved hi/lo out.
// MODE 3: MODE 2 + fused column-sum -> Ksum (Ksum zeroed by the MODE 1
//         kernel that runs earlier in the stream).
// 128x128 tile, BK=32, 256 threads, warps 2x4. Dynamic smem (72.2 KB).
// ---------------------------------------------------------------------------
#define AS 133
#define BS 37
#define GEMM_SMEM_FLOATS (2 * 32 * AS + 2 * 128 * BS + 64)
#define GEMM_SMEM_BYTES  (GEMM_SMEM_FLOATS * 4)

template<int MODE, int AHL>
__global__ __launch_bounds__(256, 2) void gemm4(
    const float* __restrict__ A, const float* __restrict__ W,
    const float* __restrict__ bias, float* __restrict__ C,
    float* __restrict__ Ksum)
{
    extern __shared__ float gsm[];
    float* AhiT = gsm;                       // [32][133]  ([k][row])
    float* AloT = AhiT + 32 * AS;            // [32][133]
    float* Bhi  = AloT + 32 * AS;            // [128][37]  ([n][k])
    float* Blo  = Bhi + 128 * BS;            // [128][37]
    float* s_cs = Blo + 128 * BS;            // [64]

    const int tid = threadIdx.x;
    const int bx = blockIdx.x, by = blockIdx.y;
    const int warp = tid >> 5, lane = tid & 31;
    const int wm = warp >> 2, wn = warp & 3;
    const int lg = lane >> 2, la = lane & 3;

    if (MODE == 1 && bx == 0 && by == 0) {
        for (int i = tid; i < NGROUP * DHEAD; i += 256) Ksum[i] = 0.f;
    }
    if (MODE == 3 && tid < 64) s_cs[tid] = 0.f;

    float acc[4][4][4] = {};

    for (int k0 = 0; k0 < DMODEL; k0 += 32) {
        // A tile: 128 rows x 32 k
        #pragma unroll
        for (int l = 0; l < 16; l++) {
            int idx = tid + l * 256;
            int r = idx >> 5, k = idx & 31;
            if (AHL) {
                float2 v = *(const float2*)(A +
                    2 * ((size_t)(by * 128 + r) * DMODEL + k0 + k));
                AhiT[k * AS + r] = v.x;
                AloT[k * AS + r] = v.y;
            } else {
                float v = A[(size_t)(by * 128 + r) * DMODEL + k0 + k];
                float h = tf32f(v);
                AhiT[k * AS + r] = h;
                AloT[k * AS + r] = tf32f(v - h);
            }
        }
        // B tile: 32 k x 128 n, split in-kernel
        #pragma unroll
        for (int l = 0; l < 16; l++) {
            int idx = tid + l * 256;
            int k = idx >> 7, n = idx & 127;
            float b = W[(size_t)(k0 + k) * DMODEL + bx * 128 + n];
            float h = tf32f(b);
            Bhi[n * BS + k] = h;
            Blo[n * BS + k] = tf32f(b - h);
        }
        __syncthreads();

        #pragma unroll
        for (int kk = 0; kk < 4; kk++) {
            uint32_t ahi[4][4], alo[4][4];
            #pragma unroll
            for (int mf = 0; mf < 4; mf++) {
                int r0 = wm * 64 + mf * 16 + lg;
                int c0 = kk * 8 + la;
                ahi[mf][0] = __float_as_uint(AhiT[c0 * AS + r0]);
                ahi[mf][1] = __float_as_uint(AhiT[c0 * AS + r0 + 8]);
                ahi[mf][2] = __float_as_uint(AhiT[(c0 + 4) * AS + r0]);
                ahi[mf][3] = __float_as_uint(AhiT[(c0 + 4) * AS + r0 + 8]);
                alo[mf][0] = __float_as_uint(AloT[c0 * AS + r0]);
                alo[mf][1] = __float_as_uint(AloT[c0 * AS + r0 + 8]);
                alo[mf][2] = __float_as_uint(AloT[(c0 + 4) * AS + r0]);
                alo[mf][3] = __float_as_uint(AloT[(c0 + 4) * AS + r0 + 8]);
            }
            #pragma unroll
            for (int nf = 0; nf < 4; nf++) {
                int n = wn * 32 + nf * 8 + lg;
                int c0 = kk * 8 + la;
                uint32_t bhi0 = __float_as_uint(Bhi[n * BS + c0]);
                uint32_t bhi1 = __float_as_uint(Bhi[n * BS + c0 + 4]);
                uint32_t blo0 = __float_as_uint(Blo[n * BS + c0]);
                uint32_t blo1 = __float_as_uint(Blo[n * BS + c0 + 4]);
                #pragma unroll
                for (int mf = 0; mf < 4; mf++) {
                    mma_tf32(acc[mf][nf], ahi[mf][0], ahi[mf][1], ahi[mf][2], ahi[mf][3], bhi0, bhi1);
                    mma_tf32(acc[mf][nf], alo[mf][0], alo[mf][1], alo[mf][2], alo[mf][3], bhi0, bhi1);
                    mma_tf32(acc[mf][nf], ahi[mf][0], ahi[mf][1], ahi[mf][2], ahi[mf][3], blo0, blo1);
                    mma_tf32(acc[mf][nf], alo[mf][0], alo[mf][1], alo[mf][2], alo[mf][3], blo0, blo1);
                }
            }
        }
        __syncthreads();
    }

    // epilogue
    float csum[4][2];
    if (MODE == 3)
        #pragma unroll
        for (int nf = 0; nf < 4; nf++) { csum[nf][0] = 0.f; csum[nf][1] = 0.f; }

    #pragma unroll
    for (int mf = 0; mf < 4; mf++) {
        int r0 = by * 128 + wm * 64 + mf * 16 + lg;
        #pragma unroll
        for (int nf = 0; nf < 4; nf++) {
            int c = bx * 128 + wn * 32 + nf * 8 + 2 * la;
            float b0 = bias[c], b1 = bias[c + 1];
            float t0 = acc[mf][nf][0] + b0;
            float t1 = acc[mf][nf][1] + b1;
            float t2 = acc[mf][nf][2] + b0;
            float t3 = acc[mf][nf][3] + b1;
            if (MODE == 3) { csum[nf][0] += t0 + t2; csum[nf][1] += t1 + t3; }
            if (MODE == 0) {
                *(float2*)(C + (size_t)r0 * DMODEL + c)       = make_float2(t0, t1);
                *(float2*)(C + (size_t)(r0 + 8) * DMODEL + c) = make_float2(t2, t3);
            } else {
                if (MODE == 1) { t0 *= QK_SCALE; t1 *= QK_SCALE; t2 *= QK_SCALE; t3 *= QK_SCALE; }
                float h0 = tf32f(t0), h1 = tf32f(t1), h2 = tf32f(t2), h3 = tf32f(t3);
                *(float4*)(C + 2 * ((size_t)r0 * DMODEL + c)) =
                    make_float4(h0, tf32f(t0 - h0), h1, tf32f(t1 - h1));
                *(float4*)(C + 2 * ((size_t)(r0 + 8) * DMODEL + c)) =
                    make_float4(h2, tf32f(t2 - h2), h3, tf32f(t3 - h3));
            }
        }
    }

    if (MODE == 3) {
        #pragma unroll
        for (int nf = 0; nf < 4; nf++) {
            atomicAdd(&s_cs[(wn * 32 + nf * 8 + 2 * la) & 63],     csum[nf][0]);
            atomicAdd(&s_cs[(wn * 32 + nf * 8 + 2 * la + 1) & 63], csum[nf][1]);
        }
        __syncthreads();
        if (tid < 64) atomicAdd(&Ksum[(by >> 1) * 64 + tid], s_cs[tid]);
    }
}

// ---------------------------------------------------------------------------
// Fused attention v3: block = (group g, 128-q tile); warp = 16 q-rows, full
// key width of each 128-key tile. Q frags in registers (loaded once, hi/lo);
// K,V pre-split interleaved in smem (pure-copy loads); P goes through smem
// as tf32 (NO shuffles); V 2x-split in PV. Z per-warp (no atomics).
// Strides are multiples of 8 (float4-safe).
// ---------------------------------------------------------------------------
#define KVS 136
#define FUSED_SMEM ((3 * 128 * KVS + 64 + 128) * 4)   // 209,664 B

__global__ __launch_bounds__(256, 1) void fused_attn(
    const float* __restrict__ Qhl, const float* __restrict__ Khl,
    const float* __restrict__ Vhl, const float* __restrict__ Ksum,
    float* __restrict__ Ohl)
{
    extern __shared__ float sm[];
    float* Ks     = sm;                    // [128][136] interleaved hi/lo
    float* Vs     = Ks + 128 * KVS;        // [128][136] interleaved hi/lo
    float* Ps     = Vs + 128 * KVS;        // [128][136] tf32 probs
    float* s_ksum = Ps + 128 * KVS;        // 64
    float* s_mean = s_ksum + 64;           // 128

    const int tid = threadIdx.x;
    const int lane = tid & 31, w = tid >> 5;
    const int lg = lane >> 2, la = lane & 3;
    const int g = blockIdx.y, qt = blockIdx.x;

    const float* Qg = Qhl + 2 * ((size_t)(g * SLEN + qt * 128)) * DHEAD;
    const float* Kg = Khl + 2 * (size_t)g * SLEN * DHEAD;
    const float* Vg = Vhl + 2 * (size_t)g * SLEN * DHEAD;

    if (tid < 64) s_ksum[tid] = Ksum[g * 64 + tid];
    __syncthreads();
    if (tid < 128) {
        const float* qr = Qg + (size_t)tid * 128;
        float a = 0.f;
        #pragma unroll
        for (int d = 0; d < 64; d++) a += (qr[2 * d] + qr[2 * d + 1]) * s_ksum[d];
        s_mean[tid] = a * (1.0f / 2048.0f);
    }

    // Q fragments (constant over key tiles): rows w*16+lg, w*16+8+lg
    uint32_t qhi[8][4], qlo[8][4];
    {
        int r0 = w * 16 + lg;
        #pragma unroll
        for (int kk = 0; kk < 8; kk++) {
            int c0 = kk * 8 + la;
            float2 p;
            p = *(const float2*)(Qg + (size_t)r0 * 128 + 2 * c0);
            qhi[kk][0] = __float_as_uint(p.x); qlo[kk][0] = __float_as_uint(p.y);
            p = *(const float2*)(Qg + (size_t)(r0 + 8) * 128 + 2 * c0);
            qhi[kk][1] = __float_as_uint(p.x); qlo[kk][1] = __float_as_uint(p.y);
            p = *(const float2*)(Qg + (size_t)r0 * 128 + 2 * (c0 + 4));
            qhi[kk][2] = __float_as_uint(p.x); qlo[kk][2] = __float_as_uint(p.y);
            p = *(const float2*)(Qg + (size_t)(r0 + 8) * 128 + 2 * (c0 + 4));
            qhi[kk][3] = __float_as_uint(p.x); qlo[kk][3] = __float_as_uint(p.y);
        }
    }
    __syncthreads();
    const float m0 = s_mean[w * 16 + lg];
    const float m1 = s_mean[w * 16 + 8 + lg];

    float oacc[8][4] = {};
    float z0 = 0.f, z1 = 0.f;

    for (int kt = 0; kt < 16; kt++) {
        // load K,V interleaved tiles: 128 rows x 128 floats each (pure copy)
        #pragma unroll
        for (int l = 0; l < 16; l++) {
            int idx = tid + l * 256;
            int r = idx >> 5, c = (idx & 31) * 4;
            *(float4*)(Ks + r * KVS + c) =
                *(const float4*)(Kg + (size_t)(kt * 128 + r) * 128 + c);
            *(float4*)(Vs + r * KVS + c) =
                *(const float4*)(Vg + (size_t)(kt * 128 + r) * 128 + c);
        }
        __syncthreads();

        // === S = Q @ K^T (3xtf32), 16 n8 chunks across the 128-key tile ===
        float sc[16][4];
        #pragma unroll
        for (int nf = 0; nf < 16; nf++)
            #pragma unroll
            for (int j = 0; j < 4; j++) sc[nf][j] = 0.f;

        #pragma unroll
        for (int kk = 0; kk < 8; kk++) {
            int kc2 = 2 * (kk * 8 + la);
            #pragma unroll
            for (int nf = 0; nf < 16; nf++) {
                int kr = nf * 8 + lg;
                float2 b0 = *(const float2*)(Ks + kr * KVS + kc2);
                float2 b1 = *(const float2*)(Ks + kr * KVS + kc2 + 8);
                uint32_t bh0 = __float_as_uint(b0.x), bh1 = __float_as_uint(b1.x);
                uint32_t bl0 = __float_as_uint(b0.y), bl1 = __float_as_uint(b1.y);
                mma_tf32(sc[nf], qhi[kk][0], qhi[kk][1], qhi[kk][2], qhi[kk][3], bh0, bh1);
                mma_tf32(sc[nf], qlo[kk][0], qlo[kk][1], qlo[kk][2], qlo[kk][3], bh0, bh1);
                mma_tf32(sc[nf], qhi[kk][0], qhi[kk][1], qhi[kk][2], qhi[kk][3], bl0, bl1);
            }
        }

        // === mask + exp; write tf32 P to smem (C-frag layout, no shuffles) ===
        {
            int r0 = w * 16 + lg;
            #pragma unroll
            for (int nf = 0; nf < 16; nf++) {
                int col = nf * 8 + 2 * la;
                float s0 = sc[nf][0], s1 = sc[nf][1], s2 = sc[nf][2], s3 = sc[nf][3];
                float p0 = (s0 > m0) ? tf32f(__expf(s0)) : 0.f;
                float p1 = (s1 > m0) ? tf32f(__expf(s1)) : 0.f;
                float p2 = (s2 > m1) ? tf32f(__expf(s2)) : 0.f;
                float p3 = (s3 > m1) ? tf32f(__expf(s3)) : 0.f;
                z0 += p0 + p1; z1 += p2 + p3;
                *(float2*)(Ps + r0 * KVS + col)       = make_float2(p0, p1);
                *(float2*)(Ps + (r0 + 8) * KVS + col) = make_float2(p2, p3);
            }
        }
        __syncwarp();   // P rows are warp-private; no block sync needed before PV

        // === O += P @ V (V 2x-split); A-frags from Ps (warp's own rows) ===
        {
            int r0 = w * 16 + lg;
            #pragma unroll
            for (int kk = 0; kk < 16; kk++) {
                int c0 = kk * 8 + la;
                uint32_t a0 = __float_as_uint(Ps[r0 * KVS + c0]);
                uint32_t a1 = __float_as_uint(Ps[(r0 + 8) * KVS + c0]);
                uint32_t a2 = __float_as_uint(Ps[r0 * KVS + c0 + 4]);
                uint32_t a3 = __float_as_uint(Ps[(r0 + 8) * KVS + c0 + 4]);
                int vr0 = (kk * 8 + la) * KVS;
                int vr1 = (kk * 8 + la + 4) * KVS;
                #pragma unroll
                for (int nf = 0; nf < 8; nf++) {
                    int vc2 = 2 * (nf * 8 + lg);
                    float2 bv0 = *(const float2*)(Vs + vr0 + vc2);
                    float2 bv1 = *(const float2*)(Vs + vr1 + vc2);
                    mma_tf32(oacc[nf], a0, a1, a2, a3,
                             __float_as_uint(bv0.x), __float_as_uint(bv1.x));
                    mma_tf32(oacc[nf], a0, a1, a2, a3,
                             __float_as_uint(bv0.y), __float_as_uint(bv1.y));
                }
            }
        }
        __syncthreads();   // protect Ks/Vs before next tile's load
    }

    // Z reduce across the 4 la-lanes (rows are warp-exclusive)
    z0 += __shfl_xor_sync(0xffffffffu, z0, 1);
    z0 += __shfl_xor_sync(0xffffffffu, z0, 2);
    z1 += __shfl_xor_sync(0xffffffffu, z1, 1);
    z1 += __shfl_xor_sync(0xffffffffu, z1, 2);
    const float iz0 = 1.f / z0, iz1 = 1.f / z1;

    // normalize + split hi/lo + write interleaved O
    float* Og = Ohl + 2 * ((size_t)(g * SLEN + qt * 128)) * DHEAD;
    int r0 = w * 16 + lg;
    #pragma unroll
    for (int nf = 0; nf < 8; nf++) {
        int c2 = 2 * (nf * 8 + 2 * la);
        float t0 = oacc[nf][0] * iz0, t1 = oacc[nf][1] * iz0;
        float h0 = tf32f(t0), h1 = tf32f(t1);
        *(float4*)(Og + (size_t)r0 * 128 + c2) =
            make_float4(h0, tf32f(t0 - h0), h1, tf32f(t1 - h1));
        float t2 = oacc[nf][2] * iz1, t3 = oacc[nf][3] * iz1;
        float h2 = tf32f(t2), h3 = tf32f(t3);
        *(float4*)(Og + (size_t)(r0 + 8) * 128 + c2) =
            make_float4(h2, tf32f(t2 - h2), h3, tf32f(t3 - h3));
    }
}

// ---------------------------------------------------------------------------
// Launch: gemmQ(0), gemmK(1), gemmV(2), fused(3 <- PROFILED), gemmO(4)
// ---------------------------------------------------------------------------
extern "C" void kernel_launch(void* const* d_in, const int* in_sizes, int n_in,
                              void* d_out, int out_size)
{
    const float* x  = (const float*)d_in[0];
    const float* y  = (const float*)d_in[1];
    const float* Wq = (const float*)d_in[2];
    const float* bq = (const float*)d_in[3];
    const float* Wk = (const float*)d_in[4];
    const float* bk = (const float*)d_in[5];
    const float* Wv = (const float*)d_in[6];
    const float* bv = (const float*)d_in[7];
    const float* Wo = (const float*)d_in[8];
    const float* bo = (const float*)d_in[9];
    float* out = (float*)d_out;

    float *Qhl, *Khl, *Vhl, *Ohl, *KsumP;
    cudaGetSymbolAddress((void**)&Qhl, g_Qhl);
    cudaGetSymbolAddress((void**)&Khl, g_Khl);
    cudaGetSymbolAddress((void**)&Vhl, g_Vhl);
    cudaGetSymbolAddress((void**)&Ohl, g_Ohl);
    cudaGetSymbolAddress((void**)&KsumP, g_Ksum);

    cudaFuncSetAttribute(fused_attn,
                         cudaFuncAttributeMaxDynamicSharedMemorySize, FUSED_SMEM);
    cudaFuncSetAttribute((gemm4<1,0>),
                         cudaFuncAttributeMaxDynamicSharedMemorySize, GEMM_SMEM_BYTES);
    cudaFuncSetAttribute((gemm4<3,0>),
                         cudaFuncAttributeMaxDynamicSharedMemorySize, GEMM_SMEM_BYTES);
    cudaFuncSetAttribute((gemm4<2,0>),
                         cudaFuncAttributeMaxDynamicSharedMemorySize, GEMM_SMEM_BYTES);
    cudaFuncSetAttribute((gemm4<0,1>),
                         cudaFuncAttributeMaxDynamicSharedMemorySize, GEMM_SMEM_BYTES);

    dim3 gProj(DMODEL / 128, MROWS / 128);     // (4, 64)

    gemm4<1,0><<<gProj, 256, GEMM_SMEM_BYTES>>>(x, Wq, bq, Qhl, KsumP);   // 0: Q + zero Ksum
    gemm4<3,0><<<gProj, 256, GEMM_SMEM_BYTES>>>(y, Wk, bk, Khl, KsumP);   // 1: K + Ksum
    gemm4<2,0><<<gProj, 256, GEMM_SMEM_BYTES>>>(y, Wv, bv, Vhl, nullptr); // 2: V
    fused_attn<<<dim3(16, NGROUP), 256, FUSED_SMEM>>>(Qhl, Khl, Vhl, KsumP, Ohl); // 3 <- profiled
    gemm4<0,1><<<gProj, 256, GEMM_SMEM_BYTES>>>(Ohl, Wo, bo, out, nullptr); // 4: output proj
}

// round 9
// speedup vs baseline: 1.4048x; 1.3445x over previous
#include <cuda_runtime.h>
#include <math.h>
#include <stdint.h>

#define SLEN   2048
#define DHEAD  64
#define NGROUP 32
#define MROWS  8192
#define DMODEL 512
#define QK_SCALE 0.04419417382415922f   // 1/sqrt(512)

// Scratch: Q,K interleaved {tf32hi,tf32lo}; V single tf32; O interleaved.
__device__ float g_Qhl[(size_t)2 * MROWS * DMODEL];
__device__ float g_Khl[(size_t)2 * MROWS * DMODEL];
__device__ float g_Vt [(size_t)MROWS * DMODEL];
__device__ float g_Ohl[(size_t)2 * MROWS * DMODEL];
__device__ float g_Ksum[NGROUP * DHEAD];

__device__ __forceinline__ uint32_t f32_to_tf32(float x) {
    uint32_t r;
    asm("cvt.rna.tf32.f32 %0, %1;" : "=r"(r) : "f"(x));
    return r;
}
__device__ __forceinline__ float tf32f(float x) {
    return __uint_as_float(f32_to_tf32(x));
}
__device__ __forceinline__ void mma_tf32(float (&c)[4],
    uint32_t a0, uint32_t a1, uint32_t a2, uint32_t a3,
    uint32_t b0, uint32_t b1)
{
    asm volatile(
        "mma.sync.aligned.m16n8k8.row.col.f32.tf32.tf32.f32 "
        "{%0,%1,%2,%3}, {%4,%5,%6,%7}, {%8,%9}, {%0,%1,%2,%3};\n"
        : "+f"(c[0]), "+f"(c[1]), "+f"(c[2]), "+f"(c[3])
        : "r"(a0), "r"(a1), "r"(a2), "r"(a3), "r"(b0), "r"(b1));
}

// ---------------------------------------------------------------------------
// Split-tf32 GEMM: C = A[8192,512] @ W[512,512] + bias.
// NMMA: 3 or 4 split terms. AHL: 0 = A fp32 (split at load), 1 = A interleaved.
// MODE 0: fp32 out. MODE 1: scale*QK_SCALE, interleaved hi/lo out; block(0,0)
//         zeroes Ksum. MODE 2: single tf32 out. MODE 3: interleaved + colsum.
// ---------------------------------------------------------------------------
#define AS 133
#define BS 37
#define GEMM_SMEM_FLOATS (2 * 32 * AS + 2 * 128 * BS + 64)
#define GEMM_SMEM_BYTES  (GEMM_SMEM_FLOATS * 4)

template<int NMMA, int MODE, int AHL>
__global__ __launch_bounds__(256, 2) void gemm_t(
    const float* __restrict__ A, const float* __restrict__ W,
    const float* __restrict__ bias, float* __restrict__ C,
    float* __restrict__ Ksum)
{
    extern __shared__ float gsm[];
    float* AhiT = gsm;                       // [32][133]  ([k][row])
    float* AloT = AhiT + 32 * AS;
    float* Bhi  = AloT + 32 * AS;            // [128][37]  ([n][k])
    float* Blo  = Bhi + 128 * BS;
    float* s_cs = Blo + 128 * BS;            // [64]

    const int tid = threadIdx.x;
    const int bx = blockIdx.x, by = blockIdx.y;
    const int warp = tid >> 5, lane = tid & 31;
    const int wm = warp >> 2, wn = warp & 3;
    const int lg = lane >> 2, la = lane & 3;

    if (MODE == 1 && bx == 0 && by == 0) {
        for (int i = tid; i < NGROUP * DHEAD; i += 256) Ksum[i] = 0.f;
    }
    if (MODE == 3 && tid < 64) s_cs[tid] = 0.f;

    float acc[4][4][4] = {};

    for (int k0 = 0; k0 < DMODEL; k0 += 32) {
        #pragma unroll
        for (int l = 0; l < 16; l++) {
            int idx = tid + l * 256;
            int r = idx >> 5, k = idx & 31;
            if (AHL) {
                float2 v = *(const float2*)(A +
                    2 * ((size_t)(by * 128 + r) * DMODEL + k0 + k));
                AhiT[k * AS + r] = v.x;
                AloT[k * AS + r] = v.y;
            } else {
                float v = A[(size_t)(by * 128 + r) * DMODEL + k0 + k];
                float h = tf32f(v);
                AhiT[k * AS + r] = h;
                AloT[k * AS + r] = tf32f(v - h);
            }
        }
        #pragma unroll
        for (int l = 0; l < 16; l++) {
            int idx = tid + l * 256;
            int k = idx >> 7, n = idx & 127;
            float b = W[(size_t)(k0 + k) * DMODEL + bx * 128 + n];
            float h = tf32f(b);
            Bhi[n * BS + k] = h;
            Blo[n * BS + k] = tf32f(b - h);
        }
        __syncthreads();

        #pragma unroll
        for (int kk = 0; kk < 4; kk++) {
            uint32_t ahi[4][4], alo[4][4];
            #pragma unroll
            for (int mf = 0; mf < 4; mf++) {
                int r0 = wm * 64 + mf * 16 + lg;
                int c0 = kk * 8 + la;
                ahi[mf][0] = __float_as_uint(AhiT[c0 * AS + r0]);
                ahi[mf][1] = __float_as_uint(AhiT[c0 * AS + r0 + 8]);
                ahi[mf][2] = __float_as_uint(AhiT[(c0 + 4) * AS + r0]);
                ahi[mf][3] = __float_as_uint(AhiT[(c0 + 4) * AS + r0 + 8]);
                alo[mf][0] = __float_as_uint(AloT[c0 * AS + r0]);
                alo[mf][1] = __float_as_uint(AloT[c0 * AS + r0 + 8]);
                alo[mf][2] = __float_as_uint(AloT[(c0 + 4) * AS + r0]);
                alo[mf][3] = __float_as_uint(AloT[(c0 + 4) * AS + r0 + 8]);
            }
            #pragma unroll
            for (int nf = 0; nf < 4; nf++) {
                int n = wn * 32 + nf * 8 + lg;
                int c0 = kk * 8 + la;
                uint32_t bhi0 = __float_as_uint(Bhi[n * BS + c0]);
                uint32_t bhi1 = __float_as_uint(Bhi[n * BS + c0 + 4]);
                uint32_t blo0 = __float_as_uint(Blo[n * BS + c0]);
                uint32_t blo1 = __float_as_uint(Blo[n * BS + c0 + 4]);
                #pragma unroll
                for (int mf = 0; mf < 4; mf++) {
                    mma_tf32(acc[mf][nf], ahi[mf][0], ahi[mf][1], ahi[mf][2], ahi[mf][3], bhi0, bhi1);
                    mma_tf32(acc[mf][nf], alo[mf][0], alo[mf][1], alo[mf][2], alo[mf][3], bhi0, bhi1);
                    mma_tf32(acc[mf][nf], ahi[mf][0], ahi[mf][1], ahi[mf][2], ahi[mf][3], blo0, blo1);
                    if (NMMA == 4)
                        mma_tf32(acc[mf][nf], alo[mf][0], alo[mf][1], alo[mf][2], alo[mf][3], blo0, blo1);
                }
            }
        }
        __syncthreads();
    }

    float csum[4][2];
    if (MODE == 3)
        #pragma unroll
        for (int nf = 0; nf < 4; nf++) { csum[nf][0] = 0.f; csum[nf][1] = 0.f; }

    #pragma unroll
    for (int mf = 0; mf < 4; mf++) {
        int r0 = by * 128 + wm * 64 + mf * 16 + lg;
        #pragma unroll
        for (int nf = 0; nf < 4; nf++) {
            int c = bx * 128 + wn * 32 + nf * 8 + 2 * la;
            float b0 = bias[c], b1 = bias[c + 1];
            float t0 = acc[mf][nf][0] + b0;
            float t1 = acc[mf][nf][1] + b1;
            float t2 = acc[mf][nf][2] + b0;
            float t3 = acc[mf][nf][3] + b1;
            if (MODE == 3) { csum[nf][0] += t0 + t2; csum[nf][1] += t1 + t3; }
            if (MODE == 0) {
                *(float2*)(C + (size_t)r0 * DMODEL + c)       = make_float2(t0, t1);
                *(float2*)(C + (size_t)(r0 + 8) * DMODEL + c) = make_float2(t2, t3);
            } else if (MODE == 2) {
                *(float2*)(C + (size_t)r0 * DMODEL + c)       = make_float2(tf32f(t0), tf32f(t1));
                *(float2*)(C + (size_t)(r0 + 8) * DMODEL + c) = make_float2(tf32f(t2), tf32f(t3));
            } else {
                if (MODE == 1) { t0 *= QK_SCALE; t1 *= QK_SCALE; t2 *= QK_SCALE; t3 *= QK_SCALE; }
                float h0 = tf32f(t0), h1 = tf32f(t1), h2 = tf32f(t2), h3 = tf32f(t3);
                *(float4*)(C + 2 * ((size_t)r0 * DMODEL + c)) =
                    make_float4(h0, tf32f(t0 - h0), h1, tf32f(t1 - h1));
                *(float4*)(C + 2 * ((size_t)(r0 + 8) * DMODEL + c)) =
                    make_float4(h2, tf32f(t2 - h2), h3, tf32f(t3 - h3));
            }
        }
    }

    if (MODE == 3) {
        #pragma unroll
        for (int nf = 0; nf < 4; nf++) {
            atomicAdd(&s_cs[(wn * 32 + nf * 8 + 2 * la) & 63],     csum[nf][0]);
            atomicAdd(&s_cs[(wn * 32 + nf * 8 + 2 * la + 1) & 63], csum[nf][1]);
        }
        __syncthreads();
        if (tid < 64) atomicAdd(&Ksum[(by >> 1) * 64 + tid], s_cs[tid]);
    }
}

// ---------------------------------------------------------------------------
// Fused attention v4: 512 threads / 16 warps. warp = (q-strip wq: 16 rows) x
// (key-half wk: 64 keys). Q hi/lo in smem (loaded once); K hi/lo in smem;
// P stored fp32 into the retired K buffer (Z summed from fp32 p, R2-style);
// PV splits 64 d-cols across wk (oacc[4][4]); V single tf32.
// All smem strides float4-safe; frag-load bank patterns conflict-free.
// ---------------------------------------------------------------------------
#define QKS 136
#define VS  72
#define FUSED_SMEM ((2 * 128 * QKS + 128 * VS + 64 + 128 + 256) * 4)

__global__ __launch_bounds__(512, 1) void fused_attn(
    const float* __restrict__ Qhl, const float* __restrict__ Khl,
    const float* __restrict__ Vt, const float* __restrict__ Ksum,
    float* __restrict__ Ohl)
{
    extern __shared__ float sm[];
    float* Qs     = sm;                    // [128][136] interleaved hi/lo
    float* KP     = Qs + 128 * QKS;        // [128][136] K tiles, then fp32 P
    float* Vs     = KP + 128 * QKS;        // [128][72] tf32
    float* s_ksum = Vs + 128 * VS;         // 64
    float* s_mean = s_ksum + 64;           // 128
    float* zsm    = s_mean + 128;          // 256

    const int tid = threadIdx.x;
    const int lane = tid & 31, warp = tid >> 5;
    const int wq = warp >> 1, wk = warp & 1;
    const int lg = lane >> 2, la = lane & 3;
    const int g = blockIdx.y, qt = blockIdx.x;

    const float* Qg = Qhl + 2 * ((size_t)(g * SLEN + qt * 128)) * DHEAD;
    const float* Kg = Khl + 2 * (size_t)g * SLEN * DHEAD;
    const float* Vg = Vt + (size_t)g * SLEN * DHEAD;

    // Q tile: 4096 float4, 8 per thread
    #pragma unroll
    for (int l = 0; l < 8; l++) {
        int idx = tid + l * 512;
        int r = idx >> 5, c = (idx & 31) * 4;
        *(float4*)(Qs + r * QKS + c) = *(const float4*)(Qg + (size_t)r * 128 + c);
    }
    if (tid < 64) s_ksum[tid] = Ksum[g * 64 + tid];
    __syncthreads();
    if (tid < 128) {
        float a = 0.f;
        #pragma unroll
        for (int d = 0; d < 64; d++)
            a += (Qs[tid * QKS + 2 * d] + Qs[tid * QKS + 2 * d + 1]) * s_ksum[d];
        s_mean[tid] = a * (1.0f / 2048.0f);
    }
    __syncthreads();

    const int r0 = wq * 16 + lg;
    const float m0 = s_mean[r0], m1 = s_mean[r0 + 8];

    float oacc[4][4] = {};
    float z0 = 0.f, z1 = 0.f;

    for (int kt = 0; kt < 16; kt++) {
        // K tile: 4096 float4 (8/thr); V tile: 2048 float4 (4/thr)
        #pragma unroll
        for (int l = 0; l < 8; l++) {
            int idx = tid + l * 512;
            int r = idx >> 5, c = (idx & 31) * 4;
            *(float4*)(KP + r * QKS + c) =
                *(const float4*)(Kg + (size_t)(kt * 128 + r) * 128 + c);
        }
        #pragma unroll
        for (int l = 0; l < 4; l++) {
            int idx = tid + l * 512;
            int r = idx >> 4, c = (idx & 15) * 4;
            *(float4*)(Vs + r * VS + c) =
                *(const float4*)(Vg + (size_t)(kt * 128 + r) * 64 + c);
        }
        __syncthreads();

        // === S = Q @ K^T (3xtf32): warp covers 16 q-rows x 64 keys ===
        float sc[8][4];
        #pragma unroll
        for (int nf = 0; nf < 8; nf++)
            #pragma unroll
            for (int j = 0; j < 4; j++) sc[nf][j] = 0.f;

        #pragma unroll
        for (int kk = 0; kk < 8; kk++) {
            int c2 = 2 * (kk * 8 + la);
            float2 q0 = *(const float2*)(Qs + r0 * QKS + c2);
            float2 q1 = *(const float2*)(Qs + (r0 + 8) * QKS + c2);
            float2 q2 = *(const float2*)(Qs + r0 * QKS + c2 + 8);
            float2 q3 = *(const float2*)(Qs + (r0 + 8) * QKS + c2 + 8);
            uint32_t qh0 = __float_as_uint(q0.x), ql0 = __float_as_uint(q0.y);
            uint32_t qh1 = __float_as_uint(q1.x), ql1 = __float_as_uint(q1.y);
            uint32_t qh2 = __float_as_uint(q2.x), ql2 = __float_as_uint(q2.y);
            uint32_t qh3 = __float_as_uint(q3.x), ql3 = __float_as_uint(q3.y);
            #pragma unroll
            for (int nf = 0; nf < 8; nf++) {
                int kr = wk * 64 + nf * 8 + lg;
                float2 b0 = *(const float2*)(KP + kr * QKS + c2);
                float2 b1 = *(const float2*)(KP + kr * QKS + c2 + 8);
                uint32_t bh0 = __float_as_uint(b0.x), bh1 = __float_as_uint(b1.x);
                uint32_t bl0 = __float_as_uint(b0.y), bl1 = __float_as_uint(b1.y);
                mma_tf32(sc[nf], qh0, qh1, qh2, qh3, bh0, bh1);
                mma_tf32(sc[nf], ql0, ql1, ql2, ql3, bh0, bh1);
                mma_tf32(sc[nf], qh0, qh1, qh2, qh3, bl0, bl1);
            }
        }
        __syncthreads();   // all warps done reading K

        // === mask + exp; P stored fp32 into KP; Z from fp32 p ===
        #pragma unroll
        for (int nf = 0; nf < 8; nf++) {
            int col = wk * 64 + nf * 8 + 2 * la;
            float p0 = (sc[nf][0] > m0) ? __expf(sc[nf][0]) : 0.f;
            float p1 = (sc[nf][1] > m0) ? __expf(sc[nf][1]) : 0.f;
            float p2 = (sc[nf][2] > m1) ? __expf(sc[nf][2]) : 0.f;
            float p3 = (sc[nf][3] > m1) ? __expf(sc[nf][3]) : 0.f;
            z0 += p0 + p1; z1 += p2 + p3;
            *(float2*)(KP + r0 * QKS + col)       = make_float2(p0, p1);
            *(float2*)(KP + (r0 + 8) * QKS + col) = make_float2(p2, p3);
        }
        __syncthreads();   // P complete (cross-warp)

        // === O += P @ V: warp covers its q-strip x 32 d-cols, all 128 keys ===
        #pragma unroll
        for (int kk = 0; kk < 16; kk++) {
            int c0 = kk * 8 + la;
            uint32_t a0 = f32_to_tf32(KP[r0 * QKS + c0]);
            uint32_t a1 = f32_to_tf32(KP[(r0 + 8) * QKS + c0]);
            uint32_t a2 = f32_to_tf32(KP[r0 * QKS + c0 + 4]);
            uint32_t a3 = f32_to_tf32(KP[(r0 + 8) * QKS + c0 + 4]);
            int vr0 = c0 * VS, vr1 = (c0 + 4) * VS;
            #pragma unroll
            for (int nf = 0; nf < 4; nf++) {
                int vc = wk * 32 + nf * 8 + lg;
                mma_tf32(oacc[nf], a0, a1, a2, a3,
                         __float_as_uint(Vs[vr0 + vc]),
                         __float_as_uint(Vs[vr1 + vc]));
            }
        }
        __syncthreads();   // protect KP/Vs before next tile load
    }

    // Z: reduce across la lanes, combine the two wk halves via smem
    z0 += __shfl_xor_sync(0xffffffffu, z0, 1);
    z0 += __shfl_xor_sync(0xffffffffu, z0, 2);
    z1 += __shfl_xor_sync(0xffffffffu, z1, 1);
    z1 += __shfl_xor_sync(0xffffffffu, z1, 2);
    if (la == 0) {
        zsm[r0 * 2 + wk]       = z0;
        zsm[(r0 + 8) * 2 + wk] = z1;
    }
    __syncthreads();
    const float iz0 = 1.f / (zsm[r0 * 2] + zsm[r0 * 2 + 1]);
    const float iz1 = 1.f / (zsm[(r0 + 8) * 2] + zsm[(r0 + 8) * 2 + 1]);

    // normalize + split hi/lo + write interleaved O
    float* Og = Ohl + 2 * ((size_t)(g * SLEN + qt * 128)) * DHEAD;
    #pragma unroll
    for (int nf = 0; nf < 4; nf++) {
        int c2 = 2 * (wk * 32 + nf * 8 + 2 * la);
        float t0 = oacc[nf][0] * iz0, t1 = oacc[nf][1] * iz0;
        float h0 = tf32f(t0), h1 = tf32f(t1);
        *(float4*)(Og + (size_t)r0 * 128 + c2) =
            make_float4(h0, tf32f(t0 - h0), h1, tf32f(t1 - h1));
        float t2 = oacc[nf][2] * iz1, t3 = oacc[nf][3] * iz1;
        float h2 = tf32f(t2), h3 = tf32f(t3);
        *(float4*)(Og + (size_t)(r0 + 8) * 128 + c2) =
            make_float4(h2, tf32f(t2 - h2), h3, tf32f(t3 - h3));
    }
}

// ---------------------------------------------------------------------------
// Launch: Q(0), K(1), V(2), fused(3 <- PROFILED), O(4)
// ---------------------------------------------------------------------------
extern "C" void kernel_launch(void* const* d_in, const int* in_sizes, int n_in,
                              void* d_out, int out_size)
{
    const float* x  = (const float*)d_in[0];
    const float* y  = (const float*)d_in[1];
    const float* Wq = (const float*)d_in[2];
    const float* bq = (const float*)d_in[3];
    const float* Wk = (const float*)d_in[4];
    const float* bk = (const float*)d_in[5];
    const float* Wv = (const float*)d_in[6];
    const float* bv = (const float*)d_in[7];
    const float* Wo = (const float*)d_in[8];
    const float* bo = (const float*)d_in[9];
    float* out = (float*)d_out;

    float *Qhl, *Khl, *Vt, *Ohl, *KsumP;
    cudaGetSymbolAddress((void**)&Qhl, g_Qhl);
    cudaGetSymbolAddress((void**)&Khl, g_Khl);
    cudaGetSymbolAddress((void**)&Vt, g_Vt);
    cudaGetSymbolAddress((void**)&Ohl, g_Ohl);
    cudaGetSymbolAddress((void**)&KsumP, g_Ksum);

    cudaFuncSetAttribute(fused_attn,
                         cudaFuncAttributeMaxDynamicSharedMemorySize, FUSED_SMEM);
    cudaFuncSetAttribute((gemm_t<4,1,0>),
                         cudaFuncAttributeMaxDynamicSharedMemorySize, GEMM_SMEM_BYTES);
    cudaFuncSetAttribute((gemm_t<4,3,0>),
                         cudaFuncAttributeMaxDynamicSharedMemorySize, GEMM_SMEM_BYTES);
    cudaFuncSetAttribute((gemm_t<3,2,0>),
                         cudaFuncAttributeMaxDynamicSharedMemorySize, GEMM_SMEM_BYTES);
    cudaFuncSetAttribute((gemm_t<3,0,1>),
                         cudaFuncAttributeMaxDynamicSharedMemorySize, GEMM_SMEM_BYTES);

    dim3 gProj(DMODEL / 128, MROWS / 128);   // (4, 64)

    gemm_t<4,1,0><<<gProj, 256, GEMM_SMEM_BYTES>>>(x, Wq, bq, Qhl, KsumP);   // 0: Q (4x) + zero Ksum
    gemm_t<4,3,0><<<gProj, 256, GEMM_SMEM_BYTES>>>(y, Wk, bk, Khl, KsumP);   // 1: K (4x) + Ksum
    gemm_t<3,2,0><<<gProj, 256, GEMM_SMEM_BYTES>>>(y, Wv, bv, Vt, nullptr);  // 2: V (3x, tf32 out)
    fused_attn<<<dim3(16, NGROUP), 512, FUSED_SMEM>>>(Qhl, Khl, Vt, KsumP, Ohl); // 3 <- profiled
    gemm_t<3,0,1><<<gProj, 256, GEMM_SMEM_BYTES>>>(Ohl, Wo, bo, out, nullptr); // 4: O (3x)
}